// round 5
// baseline (speedup 1.0000x reference)
#include <cuda_runtime.h>
#include <cstdint>

// Problem constants (from reference setup_inputs):
//   poses:       (4, 16, 16, 32, 4, 4)  float32
//   activations: (4, 16, 16, 32, 1, 1)  float32
//   pose_kernel: (3, 3, 32, 32, 4, 4)   float32
//   votes out:   (4, 14, 14, 3, 3, 32, 32, 4, 4)
//   act out:     (4, 14, 14, 3, 3, 32, 1, 1, 1)  appended after votes
// No contraction in the einsum -> votes is an elementwise broadcast product:
//   votes[b,h,w,x,y,i,o,m,n] = poses[b,h+x,w+y,i,m,n] * pk[x,y,i,o,m,n]

constexpr int B  = 4;
constexpr int H  = 16;
constexpr int W  = 16;
constexpr int OH = 14;
constexpr int OW = 14;
constexpr int KS = 3;
constexpr int IC = 32;
constexpr int OC = 32;
constexpr int AT = 16;   // 4x4 pose atom -> 512 floats (2KB) per tuple

constexpr int NCOMBO = KS * KS * IC;            // 288
constexpr int NSP    = B * OH * OW;             // 784
constexpr int NPOS   = NCOMBO * NSP;            // 225792 tuples
constexpr long long VOTES_ELEMS = (long long)NPOS * OC * AT; // 115,605,504

// TMA-staged store pipeline:
constexpr int TUP_PER_STAGE = 16;               // 32KB per stage
constexpr int STAGES        = 4;                // 64 tuples per CTA (128KB out)
constexpr int TUP_PER_CTA   = TUP_PER_STAGE * STAGES;
constexpr int NCTA          = NPOS / TUP_PER_CTA;   // 3528
constexpr int STAGE_F4      = TUP_PER_STAGE * 128;  // 2048 float4 = 32KB
constexpr int STAGE_BYTES   = STAGE_F4 * 16;        // 32768
constexpr int SMEM_BYTES    = 2 * STAGE_BYTES;      // 64KB double buffer

// Each CTA computes 64 consecutive tuple blocks into double-buffered SMEM
// (coalesced STS.128), then streams each 32KB stage to GMEM with ONE
// cp.async.bulk per stage. This removes the per-thread STG path (which held
// DRAM at ~75% across two different kernels) and replaces it with full-line
// TMA bursts SMEM->L2->DRAM.
__global__ __launch_bounds__(256) void fused_kernel(
    const float* __restrict__ poses,
    const float* __restrict__ act,
    const float* __restrict__ pk,
    float* __restrict__ votes_out,
    float* __restrict__ act_out)
{
    extern __shared__ float4 sbuf[];   // [2][STAGE_F4]

    int tid  = threadIdx.x;
    int warp = tid >> 5;
    int lane = tid & 31;
    int lane4 = lane & 3;

    long long cta_tuple0 = (long long)blockIdx.x * TUP_PER_CTA;

    const float4* pv_base = reinterpret_cast<const float4*>(poses);
    const float4* pk4     = reinterpret_cast<const float4*>(pk);

    uint32_t smem_base;
    asm("{ .reg .u64 t; cvta.to.shared.u64 t, %1; cvt.u32.u64 %0, t; }"
        : "=r"(smem_base) : "l"(sbuf));

#pragma unroll
    for (int s = 0; s < STAGES; ++s) {
        int buf = s & 1;

        if (s >= 2) {
            // Stage s-2 used this buffer; allow only the most recent (s-1)
            // bulk group to remain in flight before overwriting it.
            if (tid == 0)
                asm volatile("cp.async.bulk.wait_group.read 1;" ::: "memory");
            __syncthreads();
        }

        // 16 tuples per stage; each warp computes 2.
#pragma unroll
        for (int u = 0; u < 2; ++u) {
            int local_t = warp * 2 + u;                     // 0..15
            long long tuple = cta_tuple0 + s * TUP_PER_STAGE + local_t;
            int combo = (int)(tuple % NCOMBO);
            int sp    = (int)(tuple / NCOMBO);

            int i  = combo & 31;
            int xy = combo >> 5;
            int y  = xy % KS;
            int x  = xy / KS;

            int w  = sp % OW;
            int t2 = sp / OW;
            int h  = t2 % OH;
            int b  = t2 / OH;

            int src_pix = ((b * H + (h + x)) * W + (w + y)) * IC + i;

            // pose atom: 64B span broadcast load (L1 resident)
            float4 p = pv_base[src_pix * 4 + lane4];

            const float4* kv = pk4 + (long long)combo * 128;
            float4* o = &sbuf[buf * STAGE_F4 + local_t * 128];

#pragma unroll
            for (int j = 0; j < 4; ++j) {
                float4 k = kv[j * 32 + lane];
                float4 r;
                r.x = p.x * k.x; r.y = p.y * k.y;
                r.z = p.z * k.z; r.w = p.w * k.w;
                o[j * 32 + lane] = r;      // contiguous STS.128, conflict-free
            }

            if (lane == 0)
                act_out[tuple] = act[src_pix];
        }

        __syncthreads();

        if (tid == 0) {
            // make STS results visible to the async (TMA) proxy
            asm volatile("fence.proxy.async.shared::cta;" ::: "memory");
            const float* gdst = votes_out
                + (cta_tuple0 + (long long)s * TUP_PER_STAGE) * (OC * AT);
            uint32_t saddr = smem_base + buf * STAGE_BYTES;
            uint32_t nbytes = STAGE_BYTES;
            asm volatile(
                "cp.async.bulk.global.shared::cta.bulk_group [%0], [%1], %2;"
                :: "l"(gdst), "r"(saddr), "r"(nbytes) : "memory");
            asm volatile("cp.async.bulk.commit_group;" ::: "memory");
        }
    }

    // drain all outstanding bulk stores before the issuing thread exits
    if (tid == 0)
        asm volatile("cp.async.bulk.wait_group.read 0;" ::: "memory");
}

extern "C" void kernel_launch(void* const* d_in, const int* in_sizes, int n_in,
                              void* d_out, int out_size)
{
    const float* poses = (const float*)d_in[0];
    const float* acts  = (const float*)d_in[1];
    const float* pk    = (const float*)d_in[2];
    float* out = (float*)d_out;

    cudaFuncSetAttribute(fused_kernel,
                         cudaFuncAttributeMaxDynamicSharedMemorySize,
                         SMEM_BYTES);

    fused_kernel<<<NCTA, 256, SMEM_BYTES>>>(poses, acts, pk,
                                            out, out + VOTES_ELEMS);
}

// round 6
// speedup vs baseline: 1.0803x; 1.0803x over previous
#include <cuda_runtime.h>
#include <cstdint>

// Problem constants (from reference setup_inputs):
//   poses:       (4, 16, 16, 32, 4, 4)  float32
//   activations: (4, 16, 16, 32, 1, 1)  float32
//   pose_kernel: (3, 3, 32, 32, 4, 4)   float32
//   votes out:   (4, 14, 14, 3, 3, 32, 32, 4, 4)
//   act out:     (4, 14, 14, 3, 3, 32, 1, 1, 1)  appended after votes
// No contraction in the einsum -> votes is an elementwise broadcast product:
//   votes[b,h,w,x,y,i,o,m,n] = poses[b,h+x,w+y,i,m,n] * pk[x,y,i,o,m,n]

constexpr int B  = 4;
constexpr int H  = 16;
constexpr int W  = 16;
constexpr int OH = 14;
constexpr int OW = 14;
constexpr int KS = 3;
constexpr int IC = 32;
constexpr int OC = 32;
constexpr int AT = 16;   // 4x4 pose atom -> tuple block = 512 floats (2KB)

constexpr int NCOMBO = KS * KS * IC;             // 288
constexpr int NSP    = B * OH * OW;              // 784
constexpr int NPOS   = NCOMBO * NSP;             // 225792 tuples
constexpr long long VOTES_ELEMS = (long long)NPOS * OC * AT; // 115,605,504

// 256-bit vector ops (sm_100+): one warp instruction moves 1KB.
struct float8 { float4 a, b; };

__device__ __forceinline__ float8 ldg8(const float* p) {
    float8 r;
    asm volatile("ld.global.nc.v8.f32 {%0,%1,%2,%3,%4,%5,%6,%7}, [%8];"
                 : "=f"(r.a.x), "=f"(r.a.y), "=f"(r.a.z), "=f"(r.a.w),
                   "=f"(r.b.x), "=f"(r.b.y), "=f"(r.b.z), "=f"(r.b.w)
                 : "l"(p));
    return r;
}

__device__ __forceinline__ void stg8(float* p, const float8& v) {
    asm volatile("st.global.v8.f32 [%0], {%1,%2,%3,%4,%5,%6,%7,%8};"
                 :: "l"(p),
                    "f"(v.a.x), "f"(v.a.y), "f"(v.a.z), "f"(v.a.w),
                    "f"(v.b.x), "f"(v.b.y), "f"(v.b.z), "f"(v.b.w)
                 : "memory");
}

// R2's flat mapping (one warp per tuple, ascending contiguous write order —
// the best-measured DRAM locality) with 256-bit memory ops. Lane l covers
// output floats [l*8, l*8+8) and [256+l*8, 256+l*8+8) of the 512-float tuple
// block. The pose factor for float f is atom float (f & 15), so lane l needs
// only the (l&1)-th 32B half of the pose atom -> one broadcast v8 load.
// Per tuple: 5 memory instructions (was 9), identical bytes moved.
__global__ __launch_bounds__(256) void fused_kernel(
    const float* __restrict__ poses,
    const float* __restrict__ act,
    const float* __restrict__ pk,
    float* __restrict__ votes_out,
    float* __restrict__ act_out)
{
    int gwarp = (blockIdx.x * blockDim.x + threadIdx.x) >> 5;
    int lane  = threadIdx.x & 31;
    if (gwarp >= NPOS) return;

    int t = gwarp;
    int i = t & 31;  t >>= 5;     // in-capsule
    int y = t % KS;  t /= KS;     // kx
    int x = t % KS;  t /= KS;     // ky
    int w = t % OW;  t /= OW;
    int h = t % OH;  t /= OH;
    int b = t;

    int combo   = (x * KS + y) * IC + i;
    int src_pix = ((b * H + (h + x)) * W + (w + y)) * IC + i;

    // pose half-atom for this lane: 32B broadcast (2 distinct addrs per warp)
    float8 p = ldg8(poses + src_pix * AT + (lane & 1) * 8);

    const float* kbase = pk + (long long)combo * (OC * AT);
    float* obase = votes_out + (long long)gwarp * (OC * AT);

    float8 k0 = ldg8(kbase + lane * 8);
    float8 k1 = ldg8(kbase + 256 + lane * 8);

    float8 o0, o1;
    o0.a.x = p.a.x * k0.a.x; o0.a.y = p.a.y * k0.a.y;
    o0.a.z = p.a.z * k0.a.z; o0.a.w = p.a.w * k0.a.w;
    o0.b.x = p.b.x * k0.b.x; o0.b.y = p.b.y * k0.b.y;
    o0.b.z = p.b.z * k0.b.z; o0.b.w = p.b.w * k0.b.w;

    o1.a.x = p.a.x * k1.a.x; o1.a.y = p.a.y * k1.a.y;
    o1.a.z = p.a.z * k1.a.z; o1.a.w = p.a.w * k1.a.w;
    o1.b.x = p.b.x * k1.b.x; o1.b.y = p.b.y * k1.b.y;
    o1.b.z = p.b.z * k1.b.z; o1.b.w = p.b.w * k1.b.w;

    stg8(obase + lane * 8, o0);
    stg8(obase + 256 + lane * 8, o1);

    if (lane == 0) {
        act_out[gwarp] = act[src_pix];
    }
}

extern "C" void kernel_launch(void* const* d_in, const int* in_sizes, int n_in,
                              void* d_out, int out_size)
{
    const float* poses = (const float*)d_in[0];
    const float* acts  = (const float*)d_in[1];
    const float* pk    = (const float*)d_in[2];
    float* out = (float*)d_out;

    int total_threads = NPOS * 32;
    int threads = 256;
    int blocks = (total_threads + threads - 1) / threads;
    fused_kernel<<<blocks, threads>>>(poses, acts, pk, out, out + VOTES_ELEMS);
}

// round 7
// speedup vs baseline: 1.1118x; 1.0291x over previous
#include <cuda_runtime.h>

// Problem constants (from reference setup_inputs):
//   poses:       (4, 16, 16, 32, 4, 4)  float32
//   activations: (4, 16, 16, 32, 1, 1)  float32
//   pose_kernel: (3, 3, 32, 32, 4, 4)   float32
//   votes out:   (4, 14, 14, 3, 3, 32, 32, 4, 4)
//   act out:     (4, 14, 14, 3, 3, 32, 1, 1, 1)  appended after votes
// No contraction in the einsum -> votes is an elementwise broadcast product:
//   votes[b,h,w,x,y,i,o,m,n] = poses[b,h+x,w+y,i,m,n] * pk[x,y,i,o,m,n]
//
// Six-round conclusion: the kernel is bound by the HBM3e pure-write-stream
// ceiling (~6.0 TB/s achieved). The winning structure is the R2 flat mapping:
// one warp per tuple, ascending contiguous 512B-per-instruction write order,
// default write-back stores (lets ~60MB of tail writes stay dirty in L2),
// 85% occupancy. Register-caching k (R4), TMA bulk stores (R5), and 256-bit
// ld/st (R6) were all measured neutral-or-worse.

constexpr int B  = 4;
constexpr int H  = 16;
constexpr int W  = 16;
constexpr int OH = 14;
constexpr int OW = 14;
constexpr int KS = 3;
constexpr int IC = 32;
constexpr int OC = 32;
constexpr int AT = 16;   // 4x4 pose atom

constexpr int NPOS = B * OH * OW * KS * KS * IC;             // 225792 tuples
constexpr long long VOTES_ELEMS = (long long)NPOS * OC * AT; // 115,605,504
constexpr int THREADS = 256;
constexpr int BLOCKS  = NPOS * 32 / THREADS;                 // 28224 (exact)

// One warp per (b,h,w,ky,kx,i) tuple; the tuple's 512-float output block and
// matching pose_kernel block are both contiguous. Lane l, iter j handles
// float4 #(j*32+l): every LDG/STG.128 is a fully contiguous 512B warp
// transaction. Pose operand is atom float4 #(l&3) -> 4-way broadcast,
// L1-resident. Lane 0 writes the tuple's act_out element (fused).
__global__ __launch_bounds__(THREADS) void fused_kernel(
    const float* __restrict__ poses,
    const float* __restrict__ act,
    const float* __restrict__ pk,
    float* __restrict__ votes_out,
    float* __restrict__ act_out)
{
    int gwarp = (blockIdx.x * THREADS + threadIdx.x) >> 5;   // grid is exact
    int lane  = threadIdx.x & 31;

    int t = gwarp;
    int i = t & 31;  t >>= 5;     // in-capsule
    int y = t % KS;  t /= KS;     // kx
    int x = t % KS;  t /= KS;     // ky
    int w = t % OW;  t /= OW;
    int h = t % OH;  t /= OH;
    int b = t;

    int src_pix = ((b * H + (h + x)) * W + (w + y)) * IC + i;

    // pose atom: this lane always uses atom float4 #(lane & 3)
    float4 p = reinterpret_cast<const float4*>(poses)[src_pix * 4 + (lane & 3)];

    // kernel block for (x,y,i): 128 contiguous float4s
    const float4* kv = reinterpret_cast<const float4*>(pk)
                     + (long long)((x * KS + y) * IC + i) * (OC * AT / 4);
    // output block: 128 contiguous float4s
    float4* ov = reinterpret_cast<float4*>(votes_out)
               + (long long)gwarp * (OC * AT / 4);

#pragma unroll
    for (int j = 0; j < 4; ++j) {
        float4 k = kv[j * 32 + lane];
        float4 o;
        o.x = p.x * k.x;
        o.y = p.y * k.y;
        o.z = p.z * k.z;
        o.w = p.w * k.w;
        ov[j * 32 + lane] = o;
    }

    if (lane == 0) {
        act_out[gwarp] = act[src_pix];
    }
}

extern "C" void kernel_launch(void* const* d_in, const int* in_sizes, int n_in,
                              void* d_out, int out_size)
{
    const float* poses = (const float*)d_in[0];
    const float* acts  = (const float*)d_in[1];
    const float* pk    = (const float*)d_in[2];
    float* out = (float*)d_out;

    fused_kernel<<<BLOCKS, THREADS>>>(poses, acts, pk, out, out + VOTES_ELEMS);
}